// round 6
// baseline (speedup 1.0000x reference)
#include <cuda_runtime.h>

#define B  64
#define L  512
#define HB 768
#define HC 1024
#define H  (HB + HC)   // 1792
#define NL 7
#define NCH (H / 128)  // 14 chunks of 128 floats
#define BCH (HB / 128) // 6 bert chunks
#define SWS (H + 4)    // padded sW stride -> no bank conflicts in transpose

// Scratch (no allocations allowed).
__device__ int g_idx[B * L];
__device__ int g_count[B];
__device__ int g_ticket;

// ---------------------------------------------------------------------------
// Kernel 1: per-batch-row stable compaction via warp ballot scan.
// Also resets the work-queue ticket for kernel 2 (stream-ordered).
// ---------------------------------------------------------------------------
__global__ void build_idx_kernel(const int* __restrict__ valid) {
    int b    = blockIdx.x;
    int lane = threadIdx.x;
    if (b == 0 && lane == 0) g_ticket = 0;
    int base = b * L;

    int v[L / 32];
#pragma unroll
    for (int k = 0; k < L / 32; k++)
        v[k] = valid[base + k * 32 + lane];

    int count = 0;
#pragma unroll
    for (int k = 0; k < L / 32; k++) {
        unsigned m = __ballot_sync(0xffffffffu, v[k] != 0);
        if (v[k]) {
            int pos = count + __popc(m & ((1u << lane) - 1u));
            g_idx[base + pos] = k * 32 + lane;
        }
        count += __popc(m);
    }
    if (lane == 0) g_count[b] = count;
}

// ---------------------------------------------------------------------------
// Packed f32x2 FMA (Blackwell): two independent rn-FMAs per issue.
// ---------------------------------------------------------------------------
__device__ __forceinline__ void ffma2(unsigned long long& d,
                                      unsigned long long a,
                                      unsigned long long b) {
    asm("fma.rn.f32x2 %0, %1, %2, %0;" : "+l"(d) : "l"(a), "l"(b));
}

__device__ __forceinline__ float pairsum(unsigned long long d) {
    float lo, hi;
    asm("mov.b64 {%0, %1}, %2;" : "=f"(lo), "=f"(hi) : "l"(d));
    return lo + hi;
}

// ---------------------------------------------------------------------------
// Kernel 2: fused gather + concat + [BL,1792]x[1792,7] matmul + bias.
// TG=8 tokens/warp (halves weight-LDS) AND f32x2 h-pair accumulators
// (halves FMA issue). acc[8][7] pairs = 112 regs -> needs ~170 regs, so
// 12 warps/SM: 3 blocks x 128 threads, launch_bounds(128,3).
// Work distribution via global atomic ticket: perfect warp-level balance.
// ---------------------------------------------------------------------------
#define TPB 128
#define TG  8
#define NGROUPS ((B * L) / TG)   // 4096

__global__ __launch_bounds__(TPB, 3) void tag_kernel(
    const float* __restrict__ bert,
    const float* __restrict__ comet,
    const float* __restrict__ w,      // [H, NL] row-major
    const float* __restrict__ bias,   // [NL]
    float* __restrict__ out)          // [B, L, NL]
{
    extern __shared__ float sW[];     // [NL][SWS] transposed+padded

    for (int i = threadIdx.x; i < H * NL; i += TPB) {
        int h = i / NL;
        int n = i - h * NL;
        sW[n * SWS + h] = w[i];
    }
    __syncthreads();

    int lane = threadIdx.x & 31;
    float bias_r = (lane < NL) ? bias[lane] : 0.0f;
    int hb = lane * 4;

    const ulonglong2 zero2 = make_ulonglong2(0ull, 0ull);

    for (;;) {
        int g;
        if (lane == 0) g = atomicAdd(&g_ticket, 1);
        g = __shfl_sync(0xffffffffu, g, 0);
        if (g >= NGROUPS) break;

        int tok0 = g * TG;
        int b    = tok0 >> 9;          // / L  (TG | L, so one row per group)
        int p0   = tok0 & (L - 1);
        int cnt  = g_count[b];

        int  boff[TG];
        bool hasb[TG];
#pragma unroll
        for (int t = 0; t < TG; t++) {
            bool v  = (p0 + t) < cnt;
            hasb[t] = v;
            int j   = v ? g_idx[b * L + p0 + t] : 0;
            boff[t] = (b * L + j) * HB;
        }
        const float* crow0 = comet + (size_t)(b * L + p0) * HC;

        unsigned long long acc[TG][NL];
#pragma unroll
        for (int t = 0; t < TG; t++)
#pragma unroll
            for (int n = 0; n < NL; n++) acc[t][n] = 0ull;

#pragma unroll
        for (int c = 0; c < NCH; c++) {
            // 8 independent LDG.128 batched up front -> deep MLP.
            ulonglong2 x[TG];
#pragma unroll
            for (int t = 0; t < TG; t++) {
                if (c < BCH) {
                    x[t] = hasb[t]
                        ? *reinterpret_cast<const ulonglong2*>(
                              bert + boff[t] + c * 128 + hb)
                        : zero2;
                } else {
                    x[t] = *reinterpret_cast<const ulonglong2*>(
                        crow0 + t * HC + (c - BCH) * 128 + hb);
                }
            }

            int h = c * 128 + hb;
#pragma unroll
            for (int n = 0; n < NL; n++) {
                ulonglong2 wv =
                    *reinterpret_cast<const ulonglong2*>(&sW[n * SWS + h]);
#pragma unroll
                for (int t = 0; t < TG; t++) {
                    ffma2(acc[t][n], x[t].x, wv.x);
                    ffma2(acc[t][n], x[t].y, wv.y);
                }
            }
        }

        // --- butterfly reduce across lanes; lanes 0..6 write logits ---
#pragma unroll
        for (int t = 0; t < TG; t++) {
            float v = 0.0f;
#pragma unroll
            for (int n = 0; n < NL; n++) {
                float s = pairsum(acc[t][n]);
                s += __shfl_xor_sync(0xffffffffu, s, 16);
                s += __shfl_xor_sync(0xffffffffu, s, 8);
                s += __shfl_xor_sync(0xffffffffu, s, 4);
                s += __shfl_xor_sync(0xffffffffu, s, 2);
                s += __shfl_xor_sync(0xffffffffu, s, 1);
                if (lane == n) v = s;   // constant-index select, no spill
            }
            if (lane < NL)
                out[(size_t)(tok0 + t) * NL + lane] = v + bias_r;
        }
    }
}

// ---------------------------------------------------------------------------
extern "C" void kernel_launch(void* const* d_in, const int* in_sizes, int n_in,
                              void* d_out, int out_size) {
    const float* bert  = (const float*)d_in[0];
    const float* comet = (const float*)d_in[1];
    const int*   valid = (const int*)d_in[2];
    const float* w     = (const float*)d_in[3];
    const float* bias  = (const float*)d_in[4];
    float*       out   = (float*)d_out;

    build_idx_kernel<<<B, 32>>>(valid);

    const int smem = NL * SWS * (int)sizeof(float);  // 50288 B
    cudaFuncSetAttribute(tag_kernel,
                         cudaFuncAttributeMaxDynamicSharedMemorySize, smem);

    // 444 blocks = 3 per SM (12 warps/SM), single persistent wave;
    // ticket queue balances the 4096 groups across 1776 warps exactly.
    const int grid = 444;
    tag_kernel<<<grid, TPB, smem>>>(bert, comet, w, bias, out);
}

// round 7
// speedup vs baseline: 1.5020x; 1.5020x over previous
#include <cuda_runtime.h>

#define B  64
#define L  512
#define HB 768
#define HC 1024
#define H  (HB + HC)   // 1792
#define NL 7
#define NCH (H / 128)  // 14 chunks of 128 floats
#define BCH (HB / 128) // 6 bert chunks
#define SWS (H + 4)    // padded sW stride -> conflict-free transpose stores

// Scratch (no allocations allowed).
__device__ int g_idx[B * L];
__device__ int g_count[B];
__device__ int g_ticket;

// ---------------------------------------------------------------------------
// Kernel 1: per-batch-row stable compaction via warp ballot scan.
// Also resets the work-queue ticket for kernel 2 (stream-ordered).
// ---------------------------------------------------------------------------
__global__ void build_idx_kernel(const int* __restrict__ valid) {
    int b    = blockIdx.x;
    int lane = threadIdx.x;
    if (b == 0 && lane == 0) g_ticket = 0;
    int base = b * L;

    int v[L / 32];
#pragma unroll
    for (int k = 0; k < L / 32; k++)
        v[k] = valid[base + k * 32 + lane];

    int count = 0;
#pragma unroll
    for (int k = 0; k < L / 32; k++) {
        unsigned m = __ballot_sync(0xffffffffu, v[k] != 0);
        if (v[k]) {
            int pos = count + __popc(m & ((1u << lane) - 1u));
            g_idx[base + pos] = k * 32 + lane;
        }
        count += __popc(m);
    }
    if (lane == 0) g_count[b] = count;
}

// ---------------------------------------------------------------------------
// Packed f32x2 FMA (Blackwell): two independent rn-FMAs per issue.
// ---------------------------------------------------------------------------
__device__ __forceinline__ void ffma2(unsigned long long& d,
                                      unsigned long long a,
                                      unsigned long long b) {
    asm("fma.rn.f32x2 %0, %1, %2, %0;" : "+l"(d) : "l"(a), "l"(b));
}

__device__ __forceinline__ float pairsum(unsigned long long d) {
    float lo, hi;
    asm("mov.b64 {%0, %1}, %2;" : "=f"(lo), "=f"(hi) : "l"(d));
    return lo + hi;
}

__device__ __forceinline__ void prefetch_l2(const void* p) {
    asm volatile("prefetch.global.L2 [%0];" :: "l"(p));
}

// ---------------------------------------------------------------------------
// Kernel 2: fused gather + concat + [BL,1792]x[1792,7] matmul + bias.
// Winning config (R2-R6 sweep): TG=4 tokens/warp, f32x2 accumulators,
// 16 warps/SM (2 blocks x 256 thr). New this round:
//  - prefetch.global.L2 two chunks ahead (cuts exposed LDG latency
//    ~600 -> ~250 cyc without any register cost)
//  - atomic-ticket work queue (perfect warp balance, kills 3-vs-4 tail)
// ---------------------------------------------------------------------------
#define TPB 256
#define WPB (TPB / 32)
#define TG  4
#define OCC 2
#define NGROUPS ((B * L) / TG)   // 8192

__global__ __launch_bounds__(TPB, OCC) void tag_kernel(
    const float* __restrict__ bert,
    const float* __restrict__ comet,
    const float* __restrict__ w,      // [H, NL] row-major
    const float* __restrict__ bias,   // [NL]
    float* __restrict__ out)          // [B, L, NL]
{
    extern __shared__ float sW[];     // [NL][SWS] transposed+padded

    for (int i = threadIdx.x; i < H * NL; i += TPB) {
        int h = i / NL;
        int n = i - h * NL;
        sW[n * SWS + h] = w[i];
    }
    __syncthreads();

    int lane = threadIdx.x & 31;
    float bias_r = (lane < NL) ? bias[lane] : 0.0f;
    int hb = lane * 4;

    const ulonglong2 zero2 = make_ulonglong2(0ull, 0ull);

    for (;;) {
        int g;
        if (lane == 0) g = atomicAdd(&g_ticket, 1);
        g = __shfl_sync(0xffffffffu, g, 0);
        if (g >= NGROUPS) break;

        int tok0 = g * TG;
        int b    = tok0 >> 9;          // / L  (TG | L -> one row per group)
        int p0   = tok0 & (L - 1);
        int cnt  = g_count[b];

        int  boff[TG];                 // float offsets into bert (fits int)
        bool hasb[TG];
#pragma unroll
        for (int t = 0; t < TG; t++) {
            bool v  = (p0 + t) < cnt;
            hasb[t] = v;
            int j   = v ? g_idx[b * L + p0 + t] : 0;
            boff[t] = (b * L + j) * HB;
        }
        const float* crow0 = comet + (size_t)(b * L + p0) * HC;

        // Warm L2 for the first two chunks.
#pragma unroll
        for (int t = 0; t < TG; t++) {
            prefetch_l2(bert + boff[t] + hb);
            prefetch_l2(bert + boff[t] + 128 + hb);
        }

        unsigned long long acc[TG][NL];
#pragma unroll
        for (int t = 0; t < TG; t++)
#pragma unroll
            for (int n = 0; n < NL; n++) acc[t][n] = 0ull;

#pragma unroll
        for (int c = 0; c < NCH; c++) {
            // Prefetch chunk c+2 into L2 (no regs, no scoreboard).
            if (c + 2 < NCH) {
                int nc = c + 2;
#pragma unroll
                for (int t = 0; t < TG; t++) {
                    const float* pa = (nc < BCH)
                        ? bert + boff[t] + nc * 128 + hb
                        : crow0 + t * HC + (nc - BCH) * 128 + hb;
                    prefetch_l2(pa);
                }
            }

            // Token data for this chunk: 4 independent 16B loads.
            ulonglong2 x[TG];
#pragma unroll
            for (int t = 0; t < TG; t++) {
                if (c < BCH) {
                    x[t] = hasb[t]
                        ? *reinterpret_cast<const ulonglong2*>(
                              bert + boff[t] + c * 128 + hb)
                        : zero2;
                } else {
                    x[t] = *reinterpret_cast<const ulonglong2*>(
                        crow0 + t * HC + (c - BCH) * 128 + hb);
                }
            }

            int h = c * 128 + hb;
#pragma unroll
            for (int n = 0; n < NL; n++) {
                ulonglong2 wv =
                    *reinterpret_cast<const ulonglong2*>(&sW[n * SWS + h]);
#pragma unroll
                for (int t = 0; t < TG; t++) {
                    ffma2(acc[t][n], x[t].x, wv.x);
                    ffma2(acc[t][n], x[t].y, wv.y);
                }
            }
        }

        // --- butterfly reduce across lanes; lanes 0..6 write logits ---
#pragma unroll
        for (int t = 0; t < TG; t++) {
            float v = 0.0f;
#pragma unroll
            for (int n = 0; n < NL; n++) {
                float s = pairsum(acc[t][n]);
                s += __shfl_xor_sync(0xffffffffu, s, 16);
                s += __shfl_xor_sync(0xffffffffu, s, 8);
                s += __shfl_xor_sync(0xffffffffu, s, 4);
                s += __shfl_xor_sync(0xffffffffu, s, 2);
                s += __shfl_xor_sync(0xffffffffu, s, 1);
                if (lane == n) v = s;   // constant-index select, no spill
            }
            if (lane < NL)
                out[(size_t)(tok0 + t) * NL + lane] = v + bias_r;
        }
    }
}

// ---------------------------------------------------------------------------
extern "C" void kernel_launch(void* const* d_in, const int* in_sizes, int n_in,
                              void* d_out, int out_size) {
    const float* bert  = (const float*)d_in[0];
    const float* comet = (const float*)d_in[1];
    const int*   valid = (const int*)d_in[2];
    const float* w     = (const float*)d_in[3];
    const float* bias  = (const float*)d_in[4];
    float*       out   = (float*)d_out;

    build_idx_kernel<<<B, 32>>>(valid);

    const int smem = NL * SWS * (int)sizeof(float);  // 50288 B
    cudaFuncSetAttribute(tag_kernel,
                         cudaFuncAttributeMaxDynamicSharedMemorySize, smem);

    // 296 blocks = 2/SM (16 warps/SM), persistent; ticket queue balances
    // the 8192 groups across 2368 warps exactly.
    const int grid = 296;
    tag_kernel<<<grid, TPB, smem>>>(bert, comet, w, bias, out);
}

// round 9
// speedup vs baseline: 1.6481x; 1.0973x over previous
#include <cuda_runtime.h>
#include <cstdint>

#define B  64
#define L  512
#define HB 768
#define HC 1024
#define H  (HB + HC)   // 1792
#define NL 7
#define NCH (H / 128)  // 14 chunks of 128 floats
#define BCH (HB / 128) // 6 bert chunks
#define NP  4          // logit pairs (n0n1, n2n3, n4n5, n6+pad)
#define SWP_STRIDE (H * 8)            // bytes per np plane (pairs, 8B each)
#define SMEM_BYTES (NP * SWP_STRIDE)  // 57344

// Scratch (no allocations allowed).
__device__ int g_idx[B * L];
__device__ int g_count[B];
__device__ int g_ticket;

// ---------------------------------------------------------------------------
// Kernel 1: per-batch-row stable compaction via warp ballot scan.
// Also resets the work-queue ticket for kernel 2 (stream-ordered).
// ---------------------------------------------------------------------------
__global__ void build_idx_kernel(const int* __restrict__ valid) {
    int b    = blockIdx.x;
    int lane = threadIdx.x;
    if (b == 0 && lane == 0) g_ticket = 0;
    int base = b * L;

    int v[L / 32];
#pragma unroll
    for (int k = 0; k < L / 32; k++)
        v[k] = valid[base + k * 32 + lane];

    int count = 0;
#pragma unroll
    for (int k = 0; k < L / 32; k++) {
        unsigned m = __ballot_sync(0xffffffffu, v[k] != 0);
        if (v[k]) {
            int pos = count + __popc(m & ((1u << lane) - 1u));
            g_idx[base + pos] = k * 32 + lane;
        }
        count += __popc(m);
    }
    if (lane == 0) g_count[b] = count;
}

// ---------------------------------------------------------------------------
// Helpers: packed f32x2 ops + SMEM swizzle for the pair-weight planes.
// ---------------------------------------------------------------------------
__device__ __forceinline__ void ffma2(unsigned long long& d,
                                      unsigned long long a,
                                      unsigned long long b) {
    asm("fma.rn.f32x2 %0, %1, %2, %0;" : "+l"(d) : "l"(a), "l"(b));
}

__device__ __forceinline__ unsigned long long splat2(float x) {
    unsigned long long r;
    asm("mov.b64 %0, {%1, %1};" : "=l"(r) : "f"(x));
    return r;
}

__device__ __forceinline__ unsigned long long pack2(float lo, float hi) {
    unsigned long long r;
    asm("mov.b64 %0, {%1, %2};" : "=l"(r) : "f"(lo), "f"(hi));
    return r;
}

// XOR swizzle: lane stride is 32 B, so flip bits[4:5] by bits[7:8].
// Conflict-free for all four 8-lane phases of an LDS.128 (hand-verified).
__device__ __forceinline__ uint32_t swz(uint32_t raw) {
    return raw ^ (((raw >> 7) & 3u) << 4);
}

// ---------------------------------------------------------------------------
// Kernel 2 config.
// ---------------------------------------------------------------------------
#define TPB 256
#define TG  4
#define NGROUPS ((B * L) / TG)   // 8192

struct AccT { unsigned long long v[TG][NP]; };

// One 128-float chunk: 8 LDS.128 of paired weights (swizzled, conflict-free)
// + 16 splats + 64 FFMA2 across 4 tokens.
__device__ __forceinline__ void compute_chunk(
    int c, const float4* xv, AccT& A,
    const unsigned char* sm, int lane)
{
    uint32_t hraw = (uint32_t)(c * 1024 + lane * 32);
    uint32_t oA = swz(hraw);
    uint32_t oB = swz(hraw + 16);

    ulonglong2 wA[NP], wB[NP];
#pragma unroll
    for (int np = 0; np < NP; np++) {
        const unsigned char* p = sm + np * SWP_STRIDE;
        wA[np] = *reinterpret_cast<const ulonglong2*>(p + oA);  // pairs h, h+1
        wB[np] = *reinterpret_cast<const ulonglong2*>(p + oB);  // pairs h+2, h+3
    }
#pragma unroll
    for (int t = 0; t < TG; t++) {
        unsigned long long xs0 = splat2(xv[t].x);
        unsigned long long xs1 = splat2(xv[t].y);
        unsigned long long xs2 = splat2(xv[t].z);
        unsigned long long xs3 = splat2(xv[t].w);
#pragma unroll
        for (int np = 0; np < NP; np++) {
            ffma2(A.v[t][np], xs0, wA[np].x);
            ffma2(A.v[t][np], xs1, wA[np].y);
            ffma2(A.v[t][np], xs2, wB[np].x);
            ffma2(A.v[t][np], xs3, wB[np].y);
        }
    }
}

__global__ __launch_bounds__(TPB, 2) void tag_kernel(
    const float* __restrict__ bert,
    const float* __restrict__ comet,
    const float* __restrict__ w,      // [H, NL] row-major
    const float* __restrict__ bias,   // [NL]
    float* __restrict__ out)          // [B, L, NL]
{
    extern __shared__ unsigned char sm[];   // NP planes of H weight pairs

    // Build paired-weight planes: plane np holds {w[h][2np], w[h][2np+1]}
    // (n=7 padded with 0) at swizzled offset h*8.
    for (int i = threadIdx.x; i < NP * H; i += TPB) {
        int np = i & 3;
        int h  = i >> 2;
        float lo = w[h * NL + 2 * np];
        float hi = (2 * np + 1 < NL) ? w[h * NL + 2 * np + 1] : 0.0f;
        *reinterpret_cast<unsigned long long*>(
            sm + np * SWP_STRIDE + swz((uint32_t)(h * 8))) = pack2(lo, hi);
    }
    __syncthreads();

    int lane = threadIdx.x & 31;
    float bias_r = (lane < NL) ? bias[lane] : 0.0f;
    int hb = lane * 4;

    const float4 zero4 = make_float4(0.0f, 0.0f, 0.0f, 0.0f);

    for (;;) {
        int g;
        if (lane == 0) g = atomicAdd(&g_ticket, 1);
        g = __shfl_sync(0xffffffffu, g, 0);
        if (g >= NGROUPS) break;

        int tok0 = g * TG;
        int b    = tok0 >> 9;          // / L
        int p0   = tok0 & (L - 1);
        int cnt  = g_count[b];
        // Compaction makes valid slots a PREFIX: tokens t < nb have bert data.
        int nb = cnt - p0;
        nb = nb < 0 ? 0 : (nb > TG ? TG : nb);

        int boff[TG];
#pragma unroll
        for (int t = 0; t < TG; t++) {
            int j   = (t < nb) ? g_idx[b * L + p0 + t] : 0;
            boff[t] = (b * L + j) * HB;
        }
        const float* crow0 = comet + (size_t)(b * L + p0) * HC;

        AccT A;
#pragma unroll
        for (int t = 0; t < TG; t++)
#pragma unroll
            for (int np = 0; np < NP; np++) A.v[t][np] = 0ull;

        float4 xb[2][TG];   // double-buffered token slices

        if (nb > 0) {
            // Prime chunk 0 (bert).
#pragma unroll
            for (int t = 0; t < TG; t++)
                xb[0][t] = (t < nb)
                    ? *reinterpret_cast<const float4*>(bert + boff[t] + hb)
                    : zero4;
#pragma unroll
            for (int c = 0; c < NCH; c++) {
                if (c + 1 < NCH) {
                    int nc = c + 1;
#pragma unroll
                    for (int t = 0; t < TG; t++) {
                        if (nc < BCH) {
                            xb[(c + 1) & 1][t] = (t < nb)
                                ? *reinterpret_cast<const float4*>(
                                      bert + boff[t] + nc * 128 + hb)
                                : zero4;
                        } else {
                            xb[(c + 1) & 1][t] =
                                *reinterpret_cast<const float4*>(
                                    crow0 + t * HC + (nc - BCH) * 128 + hb);
                        }
                    }
                }
                compute_chunk(c, xb[c & 1], A, sm, lane);
            }
        } else {
            // All-invalid group: bert contribution is exactly zero -> comet only.
#pragma unroll
            for (int t = 0; t < TG; t++)
                xb[0][t] = *reinterpret_cast<const float4*>(crow0 + t * HC + hb);
#pragma unroll
            for (int cc = 0; cc < NCH - BCH; cc++) {
                if (cc + 1 < NCH - BCH) {
#pragma unroll
                    for (int t = 0; t < TG; t++)
                        xb[(cc + 1) & 1][t] =
                            *reinterpret_cast<const float4*>(
                                crow0 + t * HC + (cc + 1) * 128 + hb);
                }
                compute_chunk(BCH + cc, xb[cc & 1], A, sm, lane);
            }
        }

        // --- unpack pairs, butterfly reduce, lanes 0..6 write logits ---
#pragma unroll
        for (int t = 0; t < TG; t++) {
            float f[2 * NP];
#pragma unroll
            for (int np = 0; np < NP; np++)
                asm("mov.b64 {%0, %1}, %2;"
                    : "=f"(f[2 * np]), "=f"(f[2 * np + 1]) : "l"(A.v[t][np]));
            float v = 0.0f;
#pragma unroll
            for (int n = 0; n < NL; n++) {
                float s = f[n];
                s += __shfl_xor_sync(0xffffffffu, s, 16);
                s += __shfl_xor_sync(0xffffffffu, s, 8);
                s += __shfl_xor_sync(0xffffffffu, s, 4);
                s += __shfl_xor_sync(0xffffffffu, s, 2);
                s += __shfl_xor_sync(0xffffffffu, s, 1);
                if (lane == n) v = s;
            }
            if (lane < NL)
                out[(size_t)(tok0 + t) * NL + lane] = v + bias_r;
        }
    }
}

// ---------------------------------------------------------------------------
extern "C" void kernel_launch(void* const* d_in, const int* in_sizes, int n_in,
                              void* d_out, int out_size) {
    const float* bert  = (const float*)d_in[0];
    const float* comet = (const float*)d_in[1];
    const int*   valid = (const int*)d_in[2];
    const float* w     = (const float*)d_in[3];
    const float* bias  = (const float*)d_in[4];
    float*       out   = (float*)d_out;

    build_idx_kernel<<<B, 32>>>(valid);

    cudaFuncSetAttribute(tag_kernel,
                         cudaFuncAttributeMaxDynamicSharedMemorySize, SMEM_BYTES);

    // 296 blocks = 2/SM (16 warps/SM), persistent; ticket queue balances
    // the 8192 groups across 2368 warps exactly.
    const int grid = 296;
    tag_kernel<<<grid, TPB, SMEM_BYTES>>>(bert, comet, w, bias, out);
}